// round 10
// baseline (speedup 1.0000x reference)
#include <cuda_runtime.h>
#include <cstdint>

#define D_IN 64
#define D_OUT 64
#define EMAX 400000
#define NMAX 50000
#define CAP 64            // max degree capacity (Poisson(8): true max ~28)

typedef unsigned long long ull;

// ---------------- scratch -----------------------------------------------------
__device__ float g_w[EMAX * 8];
__device__ int   g_deg[NMAX];
__device__ int   g_slots[NMAX * CAP];

// ---------------- packed f32x2 helpers ----------------------------------------
__device__ __forceinline__ ull fma2(ull a, ull b, ull c) {
    ull d;
    asm("fma.rn.f32x2 %0, %1, %2, %3;" : "=l"(d) : "l"(a), "l"(b), "l"(c));
    return d;
}
__device__ __forceinline__ ull packf2(float lo, float hi) {
    ull r;
    asm("mov.b64 %0, {%1, %2};" : "=l"(r)
        : "r"(__float_as_uint(lo)), "r"(__float_as_uint(hi)));
    return r;
}
__device__ __forceinline__ void unpackf2(ull v, float& lo, float& hi) {
    unsigned a, b;
    asm("mov.b64 {%0, %1}, %2;" : "=r"(a), "=r"(b) : "l"(v));
    lo = __uint_as_float(a); hi = __uint_as_float(b);
}

// ============================================================================
// K1: per-edge cluster weights w[E,8] + direct edge bucketing  (unchanged)
// ============================================================================
#define SXS 257
#define K1_SMEM ((2048 + 64 * SXS + 32) * 4)

__device__ __forceinline__ void k1_finalize(
    const ull (&acc)[16], float xn, const float* knorm, int e, int E,
    const int* __restrict__ index)
{
    if (e >= E) return;
    float t[32];
#pragma unroll
    for (int p = 0; p < 16; ++p) {
        float lo, hi;
        unpackf2(acc[p], lo, hi);
        int c = 2 * p;
        float dist = fmaxf(knorm[c] + xn - 2.f * lo, 0.f);
        t[c] = __frcp_rn(1.f + dist);
        c = 2 * p + 1;
        dist = fmaxf(knorm[c] + xn - 2.f * hi, 0.f);
        t[c] = __frcp_rn(1.f + dist);
    }
    float m[8];
#pragma unroll
    for (int kk = 0; kk < 8; ++kk) m[kk] = 0.f;
#pragma unroll
    for (int h = 0; h < 4; ++h) {
        float hs = 0.f;
#pragma unroll
        for (int kk = 0; kk < 8; ++kk) hs += t[h * 8 + kk];
        float inv = __frcp_rn(hs);
#pragma unroll
        for (int kk = 0; kk < 8; ++kk) m[kk] = fmaf(t[h * 8 + kk], inv, m[kk]);
    }
    float mx = -1e30f;
#pragma unroll
    for (int kk = 0; kk < 8; ++kk) { m[kk] *= 2.5f; mx = fmaxf(mx, m[kk]); }
    float se = 0.f;
    float ex[8];
#pragma unroll
    for (int kk = 0; kk < 8; ++kk) { ex[kk] = __expf(m[kk] - mx); se += ex[kk]; }
    float inv = __frcp_rn(se);

    float4* wout = (float4*)g_w;
    wout[e * 2]     = make_float4(ex[0] * inv, ex[1] * inv, ex[2] * inv, ex[3] * inv);
    wout[e * 2 + 1] = make_float4(ex[4] * inv, ex[5] * inv, ex[6] * inv, ex[7] * inv);

    int node = index[e];
    int pos = atomicAdd(&g_deg[node], 1);
    if (pos < CAP) g_slots[node * CAP + pos] = e;
}

__global__ __launch_bounds__(128, 3) void k_weights(
    const float* __restrict__ xj, const float* __restrict__ eij,
    const int* __restrict__ index, const float* __restrict__ kc, int E)
{
    extern __shared__ float sm[];
    float* ksm   = sm;
    float* sx    = sm + 2048;
    float* knorm = sm + 2048 + 64 * SXS;
    const int tid = threadIdx.x;

    for (int i = tid; i < 2048; i += 128) {
        int c = i >> 6, d = i & 63;
        ksm[d * 32 + c] = kc[i];
    }
    __syncthreads();
    if (tid < 32) {
        float s = 0.f;
        for (int d = 0; d < 64; ++d) { float v = ksm[d * 32 + tid]; s = fmaf(v, v, s); }
        knorm[tid] = s;
    }

    const int e0 = blockIdx.x * 256;
    const float4* xj4 = (const float4*)xj;
    const float4* ei4 = (const float4*)eij;
    const long base4 = (long)e0 * 16;
#pragma unroll
    for (int i = 0; i < 32; ++i) {
        int f = i * 128 + tid;
        int e = f >> 4, dq = f & 15;
        float4 a = make_float4(0.f, 0.f, 0.f, 0.f);
        if (e0 + e < E) {
            float4 xa = xj4[base4 + f];
            float4 xb = ei4[base4 + f];
            a.x = xa.x + xb.x; a.y = xa.y + xb.y; a.z = xa.z + xb.z; a.w = xa.w + xb.w;
        }
        sx[(dq * 4 + 0) * SXS + e] = a.x;
        sx[(dq * 4 + 1) * SXS + e] = a.y;
        sx[(dq * 4 + 2) * SXS + e] = a.z;
        sx[(dq * 4 + 3) * SXS + e] = a.w;
    }
    __syncthreads();

    ull acca[16], accb[16];
#pragma unroll
    for (int i = 0; i < 16; ++i) { acca[i] = 0ull; accb[i] = 0ull; }
    float xna = 0.f, xnb = 0.f;

#pragma unroll 2
    for (int d = 0; d < 64; ++d) {
        float xa = sx[d * SXS + tid];
        float xb = sx[d * SXS + 128 + tid];
        xna = fmaf(xa, xa, xna);
        xnb = fmaf(xb, xb, xnb);
        ull xa2 = packf2(xa, xa);
        ull xb2 = packf2(xb, xb);
        const longlong2* kr = (const longlong2*)(ksm + d * 32);
#pragma unroll
        for (int p = 0; p < 8; ++p) {
            longlong2 kk = kr[p];
            acca[2 * p]     = fma2(xa2, (ull)kk.x, acca[2 * p]);
            acca[2 * p + 1] = fma2(xa2, (ull)kk.y, acca[2 * p + 1]);
            accb[2 * p]     = fma2(xb2, (ull)kk.x, accb[2 * p]);
            accb[2 * p + 1] = fma2(xb2, (ull)kk.y, accb[2 * p + 1]);
        }
    }

    k1_finalize(acca, xna, knorm, e0 + tid, E, index);
    k1_finalize(accb, xnb, knorm, e0 + 128 + tid, E, index);
}

// ============================================================================
// K4: warp-specialized producer/consumer, 512 threads, 1 block/SM, 16-node tile
//   tid <  256: consumers — GEMM tile t from A[p], write out (bias+leaky)
//   tid >= 256: producers — gather tile t+grid into A[p^1]
//   producer warp pw (0..7): nodes pw*2, pw*2+1 of the tile, FULL 512-wide rows
// smem: Wsm[512*64] 128KB + A[2][16][520] 65KB + bias = 197.9KB -> 1 block/SM
// ============================================================================
#define AST 520
#define RED_STR 68
#define K4_SMEM ((32768 + 32 * AST + 64) * 4)

__device__ __forceinline__ void gather_full(
    const ull* __restrict__ msg2, const longlong2* __restrict__ gw4,
    float* Adst, int n0, int N, int pw, int lane)
{
    const unsigned FULL = 0xffffffffu;
    const int nb = n0 + pw * 2;

    int degv = 0;
    if (lane < 2) {
        int idx = nb + lane;
        degv = (idx < N) ? g_deg[idx] : 0;
    }
    int d_q[2];
#pragma unroll
    for (int q = 0; q < 2; ++q) {
        int d = __shfl_sync(FULL, degv, q);
        d_q[q] = (d > CAP) ? CAP : d;
    }
    int ids[2];
#pragma unroll
    for (int q = 0; q < 2; ++q)
        ids[q] = (lane < d_q[q]) ? g_slots[(nb + q) * CAP + lane] : 0;

#pragma unroll
    for (int q = 0; q < 2; ++q) {
        ull acc2[8];
#pragma unroll
        for (int z = 0; z < 8; ++z) acc2[z] = 0ull;
        const int deg = d_q[q];
        int myE = ids[q];
        for (int p0 = 0; p0 < deg; p0 += 32) {
            if (p0 > 0) myE = (lane < deg - p0) ? g_slots[(nb + q) * CAP + p0 + lane] : 0;
            const int cnt = min(32, deg - p0);
            for (int j0 = 0; j0 < cnt; j0 += 4) {
                ull m2[4]; longlong2 wwa[4], wwb[4];
#pragma unroll
                for (int t = 0; t < 4; ++t) {
                    int e = __shfl_sync(FULL, myE, (j0 + t) & 31);
                    m2[t]  = msg2[(long)e * 32 + lane];
                    wwa[t] = gw4[(long)e * 2];
                    wwb[t] = gw4[(long)e * 2 + 1];
                }
                const int jn = min(4, cnt - j0);
#pragma unroll
                for (int t = 0; t < 4; ++t) {
                    if (t < jn) {
                        float mxv, myv;
                        unpackf2(m2[t], mxv, myv);
                        ull mxx = packf2(mxv, mxv);
                        ull myy = packf2(myv, myv);
                        acc2[0] = fma2((ull)wwa[t].x, mxx, acc2[0]);
                        acc2[1] = fma2((ull)wwa[t].x, myy, acc2[1]);
                        acc2[2] = fma2((ull)wwa[t].y, mxx, acc2[2]);
                        acc2[3] = fma2((ull)wwa[t].y, myy, acc2[3]);
                        acc2[4] = fma2((ull)wwb[t].x, mxx, acc2[4]);
                        acc2[5] = fma2((ull)wwb[t].x, myy, acc2[5]);
                        acc2[6] = fma2((ull)wwb[t].y, mxx, acc2[6]);
                        acc2[7] = fma2((ull)wwb[t].y, myy, acc2[7]);
                    }
                }
            }
        }
        // acc2[kp*2+c] = (A[k=2kp][2lane+c], A[k=2kp+1][2lane+c])
        float* arow = Adst + (pw * 2 + q) * AST;
#pragma unroll
        for (int kp = 0; kp < 4; ++kp) {
#pragma unroll
            for (int c = 0; c < 2; ++c) {
                float a, b;
                unpackf2(acc2[kp * 2 + c], a, b);
                arow[(2 * kp) * 64 + 2 * lane + c]     = a;
                arow[(2 * kp + 1) * 64 + 2 * lane + c] = b;
            }
        }
    }
}

__device__ __forceinline__ void gemm_tile(
    const float* __restrict__ Wsm, float* Ab, const float* __restrict__ bsm,
    float* __restrict__ out, int n0, int N, int tid)
{
    const int iq  = tid >> 6;      // i quarter of 512 (128 each)
    const int t64 = tid & 63;
    const int rg  = t64 >> 3;      // rows rg, rg+8
    const int cg  = t64 & 7;
    const int cA  = cg * 4;
    const int cB  = 32 + cg * 4;

    ull cacc[8];
#pragma unroll
    for (int z = 0; z < 8; ++z) cacc[z] = 0ull;
    const int ibase = iq * 128;
#pragma unroll 4
    for (int i = 0; i < 128; i += 4) {
        float4 a0 = *(const float4*)(Ab + rg * AST + ibase + i);
        float4 a1 = *(const float4*)(Ab + (rg + 8) * AST + ibase + i);
#pragma unroll
        for (int t = 0; t < 4; ++t) {
            const float* wr = Wsm + (ibase + i + t) * 64;
            longlong2 w0 = *(const longlong2*)(wr + cA);
            longlong2 w1 = *(const longlong2*)(wr + cB);
            float av0 = (&a0.x)[t];
            float av1 = (&a1.x)[t];
            ull av02 = packf2(av0, av0);
            ull av12 = packf2(av1, av1);
            cacc[0] = fma2(av02, (ull)w0.x, cacc[0]);
            cacc[1] = fma2(av02, (ull)w0.y, cacc[1]);
            cacc[2] = fma2(av02, (ull)w1.x, cacc[2]);
            cacc[3] = fma2(av02, (ull)w1.y, cacc[3]);
            cacc[4] = fma2(av12, (ull)w0.x, cacc[4]);
            cacc[5] = fma2(av12, (ull)w0.y, cacc[5]);
            cacc[6] = fma2(av12, (ull)w1.x, cacc[6]);
            cacc[7] = fma2(av12, (ull)w1.y, cacc[7]);
        }
    }
    asm volatile("bar.sync 1, 256;" ::: "memory");   // consumers: A reads done

    float* red = Ab;   // reuse consumed A buffer: 3 partials x 16 rows x RED_STR
    if (iq > 0) {
#pragma unroll
        for (int r = 0; r < 2; ++r) {
            const int row = rg + 8 * r;
            const int base = ((iq - 1) * 16 + row) * RED_STR;
            float y0, y1, y2, y3;
            unpackf2(cacc[r * 4 + 0], y0, y1);
            unpackf2(cacc[r * 4 + 1], y2, y3);
            *(float4*)(red + base + cA) = make_float4(y0, y1, y2, y3);
            unpackf2(cacc[r * 4 + 2], y0, y1);
            unpackf2(cacc[r * 4 + 3], y2, y3);
            *(float4*)(red + base + cB) = make_float4(y0, y1, y2, y3);
        }
    }
    asm volatile("bar.sync 1, 256;" ::: "memory");
    if (iq == 0) {
#pragma unroll
        for (int r = 0; r < 2; ++r) {
            const int row = rg + 8 * r;
            const int nn = n0 + row;
            if (nn < N) {
                float y[8];
                unpackf2(cacc[r * 4 + 0], y[0], y[1]);
                unpackf2(cacc[r * 4 + 1], y[2], y[3]);
                unpackf2(cacc[r * 4 + 2], y[4], y[5]);
                unpackf2(cacc[r * 4 + 3], y[6], y[7]);
#pragma unroll
                for (int p = 0; p < 3; ++p) {
                    const int base = (p * 16 + row) * RED_STR;
                    float4 v0 = *(const float4*)(red + base + cA);
                    float4 v1 = *(const float4*)(red + base + cB);
                    y[0] += v0.x; y[1] += v0.y; y[2] += v0.z; y[3] += v0.w;
                    y[4] += v1.x; y[5] += v1.y; y[6] += v1.z; y[7] += v1.w;
                }
                y[0] += bsm[cA + 0]; y[1] += bsm[cA + 1];
                y[2] += bsm[cA + 2]; y[3] += bsm[cA + 3];
                y[4] += bsm[cB + 0]; y[5] += bsm[cB + 1];
                y[6] += bsm[cB + 2]; y[7] += bsm[cB + 3];
#pragma unroll
                for (int j = 0; j < 8; ++j)
                    y[j] = (y[j] >= 0.f) ? y[j] : 0.01f * y[j];
                *(float4*)(out + (long)nn * 64 + cA) = make_float4(y[0], y[1], y[2], y[3]);
                *(float4*)(out + (long)nn * 64 + cB) = make_float4(y[4], y[5], y[6], y[7]);
            }
        }
    }
}

__global__ __launch_bounds__(512, 1) void k_agg_gemm(
    const float* __restrict__ msg, const float* __restrict__ W,
    const float* __restrict__ bias, float* __restrict__ out,
    int N, int nTiles)
{
    extern __shared__ float sm[];
    float* Wsm = sm;                        // 32768 floats
    float* A0  = sm + 32768;                // 16*520
    float* A1  = sm + 32768 + 16 * AST;     // 16*520
    float* bsm = sm + 32768 + 32 * AST;     // 64
    const int tid = threadIdx.x;

    for (int i = tid; i < 8192; i += 512) ((float4*)Wsm)[i] = ((const float4*)W)[i];
    if (tid < 64) bsm[tid] = bias[tid];
    __syncthreads();

    const ull* msg2 = (const ull*)msg;
    const longlong2* gw4 = (const longlong2*)g_w;
    const bool prod = (tid >= 256);
    const int lane = tid & 31;
    const int pw = (tid >> 5) - 8;          // producer warp id 0..7

    float* Ab[2] = {A0, A1};

    // prologue: gather first tile into A0
    if (prod) gather_full(msg2, gw4, A0, blockIdx.x * 16, N, pw, lane);
    __syncthreads();

    int p = 0;
    for (int tile = blockIdx.x; tile < nTiles; tile += gridDim.x) {
        if (prod) {
            int nt = tile + gridDim.x;
            if (nt < nTiles)
                gather_full(msg2, gw4, Ab[p ^ 1], nt * 16, N, pw, lane);
        } else {
            gemm_tile(Wsm, Ab[p], bsm, out, tile * 16, N, tid);
        }
        __syncthreads();
        p ^= 1;
    }
}

// ============================================================================
// launch
// ============================================================================
extern "C" void kernel_launch(void* const* d_in, const int* in_sizes, int n_in,
                              void* d_out, int out_size)
{
    const float* msg = (const float*)d_in[0];
    const float* xj  = (const float*)d_in[2];
    const float* eij = (const float*)d_in[3];
    const int*   idx = (const int*)d_in[4];
    const float* kc  = (const float*)d_in[6];
    const float* W   = (const float*)d_in[7];
    const float* b   = (const float*)d_in[8];
    float* out = (float*)d_out;

    const int E = in_sizes[0] / 64;
    const int N = out_size / 64;

    void* degp = nullptr;
    cudaGetSymbolAddress(&degp, g_deg);
    cudaMemsetAsync(degp, 0, (size_t)N * sizeof(int), 0);

    cudaFuncSetAttribute(k_weights, cudaFuncAttributeMaxDynamicSharedMemorySize, K1_SMEM);
    cudaFuncSetAttribute(k_agg_gemm, cudaFuncAttributeMaxDynamicSharedMemorySize, K4_SMEM);

    int eb = (E + 255) / 256;
    k_weights<<<eb, 128, K1_SMEM>>>(xj, eij, idx, kc, E);

    int sms = 148;
    cudaDeviceGetAttribute(&sms, cudaDevAttrMultiProcessorCount, 0);
    int nTiles = (N + 15) / 16;
    int grid = sms < nTiles ? sms : nTiles;
    k_agg_gemm<<<grid, 512, K4_SMEM>>>(msg, W, b, out, N, nTiles);
}

// round 12
// speedup vs baseline: 1.1613x; 1.1613x over previous
#include <cuda_runtime.h>
#include <cstdint>

#define D_IN 64
#define D_OUT 64
#define EMAX 400000
#define NMAX 50000
#define CAP 64            // max degree capacity (Poisson(8): true max ~28)

typedef unsigned long long ull;

// ---------------- scratch -----------------------------------------------------
__device__ float g_w[EMAX * 8];
__device__ int   g_deg[NMAX];
__device__ int   g_slots[NMAX * CAP];
__device__ float g_part[2][NMAX * 64];
__device__ int   g_ticket[2048];          // .bss zero; reset to 0 by consumers

// ---------------- packed f32x2 helpers ----------------------------------------
__device__ __forceinline__ ull fma2(ull a, ull b, ull c) {
    ull d;
    asm("fma.rn.f32x2 %0, %1, %2, %3;" : "=l"(d) : "l"(a), "l"(b), "l"(c));
    return d;
}
__device__ __forceinline__ ull packf2(float lo, float hi) {
    ull r;
    asm("mov.b64 %0, {%1, %2};" : "=l"(r)
        : "r"(__float_as_uint(lo)), "r"(__float_as_uint(hi)));
    return r;
}
__device__ __forceinline__ void unpackf2(ull v, float& lo, float& hi) {
    unsigned a, b;
    asm("mov.b64 {%0, %1}, %2;" : "=r"(a), "=r"(b) : "l"(v));
    lo = __uint_as_float(a); hi = __uint_as_float(b);
}

// ============================================================================
// K1: per-edge cluster weights w[E,8] + direct edge bucketing
// v3: 256 threads, 1 edge/thread, d-split 2 phases over a 32-d sx buffer.
// smem: ksm[2048] + knorm[32] + sx[32][257] = 41.2KB -> 3 blocks/SM (24 warps)
// ============================================================================
#define SXS 257
#define K1_SMEM ((2048 + 32 + 32 * SXS) * 4)

__device__ __forceinline__ void k1_finalize(
    const ull (&acc)[16], float xn, const float* knorm, int e, int E,
    const int* __restrict__ index)
{
    if (e >= E) return;
    float t[32];
#pragma unroll
    for (int p = 0; p < 16; ++p) {
        float lo, hi;
        unpackf2(acc[p], lo, hi);
        int c = 2 * p;
        float dist = fmaxf(knorm[c] + xn - 2.f * lo, 0.f);
        t[c] = __frcp_rn(1.f + dist);
        c = 2 * p + 1;
        dist = fmaxf(knorm[c] + xn - 2.f * hi, 0.f);
        t[c] = __frcp_rn(1.f + dist);
    }
    float m[8];
#pragma unroll
    for (int kk = 0; kk < 8; ++kk) m[kk] = 0.f;
#pragma unroll
    for (int h = 0; h < 4; ++h) {
        float hs = 0.f;
#pragma unroll
        for (int kk = 0; kk < 8; ++kk) hs += t[h * 8 + kk];
        float inv = __frcp_rn(hs);
#pragma unroll
        for (int kk = 0; kk < 8; ++kk) m[kk] = fmaf(t[h * 8 + kk], inv, m[kk]);
    }
    float mx = -1e30f;
#pragma unroll
    for (int kk = 0; kk < 8; ++kk) { m[kk] *= 2.5f; mx = fmaxf(mx, m[kk]); }
    float se = 0.f;
    float ex[8];
#pragma unroll
    for (int kk = 0; kk < 8; ++kk) { ex[kk] = __expf(m[kk] - mx); se += ex[kk]; }
    float inv = __frcp_rn(se);

    float4* wout = (float4*)g_w;
    wout[e * 2]     = make_float4(ex[0] * inv, ex[1] * inv, ex[2] * inv, ex[3] * inv);
    wout[e * 2 + 1] = make_float4(ex[4] * inv, ex[5] * inv, ex[6] * inv, ex[7] * inv);

    int node = index[e];
    int pos = atomicAdd(&g_deg[node], 1);
    if (pos < CAP) g_slots[node * CAP + pos] = e;
}

__global__ __launch_bounds__(256, 3) void k_weights(
    const float* __restrict__ xj, const float* __restrict__ eij,
    const int* __restrict__ index, const float* __restrict__ kc, int E)
{
    extern __shared__ float sm[];
    float* ksm   = sm;           // 2048: ksm[d*32+c]
    float* knorm = sm + 2048;    // 32
    float* sx    = sm + 2080;    // 32 * 257
    const int tid = threadIdx.x;

    // k transposed
    for (int i = tid; i < 2048; i += 256) {
        int c = i >> 6, d = i & 63;
        ksm[d * 32 + c] = kc[i];
    }
    __syncthreads();
    if (tid < 32) {
        float s = 0.f;
        for (int d = 0; d < 64; ++d) { float v = ksm[d * 32 + tid]; s = fmaf(v, v, s); }
        knorm[tid] = s;
    }

    const int e0 = blockIdx.x * 256;
    const int e  = e0 + tid;
    const float4* xj4 = (const float4*)xj;
    const float4* ei4 = (const float4*)eij;
    const long base4 = (long)e0 * 16;

    ull acc[16];
#pragma unroll
    for (int i = 0; i < 16; ++i) acc[i] = 0ull;
    float xn = 0.f;

#pragma unroll
    for (int ph = 0; ph < 2; ++ph) {
        __syncthreads();   // sx free (and knorm visible after first)
        // stage 32 d-values for 256 edges
#pragma unroll
        for (int i = 0; i < 8; ++i) {
            int f = i * 256 + tid;
            int eL = f >> 3, dq = f & 7;
            float4 a = make_float4(0.f, 0.f, 0.f, 0.f);
            if (e0 + eL < E) {
                float4 xa = xj4[base4 + (long)eL * 16 + ph * 8 + dq];
                float4 xb = ei4[base4 + (long)eL * 16 + ph * 8 + dq];
                a.x = xa.x + xb.x; a.y = xa.y + xb.y;
                a.z = xa.z + xb.z; a.w = xa.w + xb.w;
            }
            sx[(dq * 4 + 0) * SXS + eL] = a.x;
            sx[(dq * 4 + 1) * SXS + eL] = a.y;
            sx[(dq * 4 + 2) * SXS + eL] = a.z;
            sx[(dq * 4 + 3) * SXS + eL] = a.w;
        }
        __syncthreads();
        // accumulate dots over this 32-d range
#pragma unroll 2
        for (int d = 0; d < 32; ++d) {
            float xv = sx[d * SXS + tid];
            xn = fmaf(xv, xv, xn);
            ull xv2 = packf2(xv, xv);
            const longlong2* kr = (const longlong2*)(ksm + (ph * 32 + d) * 32);
#pragma unroll
            for (int p = 0; p < 8; ++p) {
                longlong2 kk = kr[p];
                acc[2 * p]     = fma2(xv2, (ull)kk.x, acc[2 * p]);
                acc[2 * p + 1] = fma2(xv2, (ull)kk.y, acc[2 * p + 1]);
            }
        }
    }

    k1_finalize(acc, xn, knorm, e, E, index);
}

// ============================================================================
// K4: k-split gather + GEMM + fused cross-block combine (R8 proven version)
// smem: Whalf[256*64] 64KB + A[32][260] 33.3KB + bias + flag -> 2 blocks/SM
// ============================================================================
#define AST 260
#define RED_STR 68
#define K4_SMEM ((16384 + 32 * AST + 68) * 4)

__global__ __launch_bounds__(256, 2) void k_agg_gemm(
    const float* __restrict__ msg, const float* __restrict__ W,
    const float* __restrict__ bias, float* __restrict__ out,
    int N, int nTiles)
{
    extern __shared__ float sm[];
    float* Wsm = sm;                       // 16384
    float* A   = sm + 16384;               // 32*260
    float* bsm = sm + 16384 + 32 * AST;    // 64
    int*   sflag = (int*)(bsm + 64);       // 1
    const int tid = threadIdx.x;
    const int lane = tid & 31, wid = tid >> 5;
    const unsigned FULL = 0xffffffffu;
    const int half = blockIdx.x & 1;
    const int pairId = blockIdx.x >> 1;
    const int nPairs = gridDim.x >> 1;

    const float4* Wsrc = (const float4*)(W + half * 256 * 64);
    for (int i = tid; i < 4096; i += 256) ((float4*)Wsm)[i] = Wsrc[i];
    if (tid < 64) bsm[tid] = bias[tid];
    __syncthreads();

    const ull* msg2 = (const ull*)msg;
    const longlong2* gw4 = (const longlong2*)g_w;
    float* mypart = g_part[half];
    const float* otherpart = g_part[half ^ 1];

    const int iq  = tid >> 6;
    const int t64 = tid & 63;
    const int rg  = t64 >> 3;
    const int cg  = t64 & 7;
    const int cA  = cg * 4;
    const int cB  = 32 + cg * 4;

    for (int tile = pairId; tile < nTiles; tile += nPairs) {
        const int n0 = tile * 32;

        const int nb = n0 + wid * 4;
        int degv = 0;
        if (lane < 4) {
            int idx = nb + lane;
            degv = (idx < N) ? g_deg[idx] : 0;
        }
        int d_q[4];
#pragma unroll
        for (int q = 0; q < 4; ++q) {
            int d = __shfl_sync(FULL, degv, q);
            d_q[q] = (d > CAP) ? CAP : d;
        }
        int ids[4];
#pragma unroll
        for (int q = 0; q < 4; ++q)
            ids[q] = (lane < d_q[q]) ? g_slots[(nb + q) * CAP + lane] : 0;

        for (int q = 0; q < 4; ++q) {
            const int nl = wid * 4 + q;
            ull acc2[4] = {0ull, 0ull, 0ull, 0ull};
            const int deg = d_q[q];
            int myE = ids[q];
            for (int p0 = 0; p0 < deg; p0 += 32) {
                if (p0 > 0) myE = (lane < deg - p0) ? g_slots[(nb + q) * CAP + p0 + lane] : 0;
                const int cnt = min(32, deg - p0);
                for (int j0 = 0; j0 < cnt; j0 += 8) {
                    ull m2[8]; longlong2 ww[8];
#pragma unroll
                    for (int t = 0; t < 8; ++t) {
                        int e = __shfl_sync(FULL, myE, (j0 + t) & 31);
                        m2[t] = msg2[(long)e * 32 + lane];
                        ww[t] = gw4[(long)e * 2 + half];
                    }
                    const int jn = min(8, cnt - j0);
#pragma unroll
                    for (int t = 0; t < 8; ++t) {
                        if (t < jn) {
                            float mxv, myv;
                            unpackf2(m2[t], mxv, myv);
                            ull mxx = packf2(mxv, mxv);
                            ull myy = packf2(myv, myv);
                            acc2[0] = fma2((ull)ww[t].x, mxx, acc2[0]);
                            acc2[1] = fma2((ull)ww[t].x, myy, acc2[1]);
                            acc2[2] = fma2((ull)ww[t].y, mxx, acc2[2]);
                            acc2[3] = fma2((ull)ww[t].y, myy, acc2[3]);
                        }
                    }
                }
            }
            float* arow = A + nl * AST;
#pragma unroll
            for (int kp = 0; kp < 2; ++kp) {
#pragma unroll
                for (int c = 0; c < 2; ++c) {
                    float a, b;
                    unpackf2(acc2[kp * 2 + c], a, b);
                    arow[(2 * kp) * 64 + 2 * lane + c]     = a;
                    arow[(2 * kp + 1) * 64 + 2 * lane + c] = b;
                }
            }
        }
        __syncthreads();

        ull cacc[16];
#pragma unroll
        for (int z = 0; z < 16; ++z) cacc[z] = 0ull;
        const int ibase = iq * 64;
#pragma unroll 4
        for (int i = 0; i < 64; i += 4) {
            float4 ar[4];
#pragma unroll
            for (int r = 0; r < 4; ++r)
                ar[r] = *(const float4*)(A + (rg + 8 * r) * AST + ibase + i);
#pragma unroll
            for (int t = 0; t < 4; ++t) {
                const float* wr = Wsm + (ibase + i + t) * 64;
                longlong2 w0 = *(const longlong2*)(wr + cA);
                longlong2 w1 = *(const longlong2*)(wr + cB);
#pragma unroll
                for (int r = 0; r < 4; ++r) {
                    float av = (&ar[r].x)[t];
                    ull av2 = packf2(av, av);
                    cacc[r * 4 + 0] = fma2(av2, (ull)w0.x, cacc[r * 4 + 0]);
                    cacc[r * 4 + 1] = fma2(av2, (ull)w0.y, cacc[r * 4 + 1]);
                    cacc[r * 4 + 2] = fma2(av2, (ull)w1.x, cacc[r * 4 + 2]);
                    cacc[r * 4 + 3] = fma2(av2, (ull)w1.y, cacc[r * 4 + 3]);
                }
            }
        }
        __syncthreads();

        float* red = A;
        if (iq > 0) {
#pragma unroll
            for (int r = 0; r < 4; ++r) {
                const int row = rg + 8 * r;
                const int base = ((iq - 1) * 32 + row) * RED_STR;
                float y0, y1, y2, y3;
                unpackf2(cacc[r * 4 + 0], y0, y1);
                unpackf2(cacc[r * 4 + 1], y2, y3);
                *(float4*)(red + base + cA) = make_float4(y0, y1, y2, y3);
                unpackf2(cacc[r * 4 + 2], y0, y1);
                unpackf2(cacc[r * 4 + 3], y2, y3);
                *(float4*)(red + base + cB) = make_float4(y0, y1, y2, y3);
            }
        }
        __syncthreads();

        float yv[4][8];
        if (iq == 0) {
#pragma unroll
            for (int r = 0; r < 4; ++r) {
                const int row = rg + 8 * r;
                unpackf2(cacc[r * 4 + 0], yv[r][0], yv[r][1]);
                unpackf2(cacc[r * 4 + 1], yv[r][2], yv[r][3]);
                unpackf2(cacc[r * 4 + 2], yv[r][4], yv[r][5]);
                unpackf2(cacc[r * 4 + 3], yv[r][6], yv[r][7]);
#pragma unroll
                for (int p = 0; p < 3; ++p) {
                    const int base = (p * 32 + row) * RED_STR;
                    float4 v0 = *(const float4*)(red + base + cA);
                    float4 v1 = *(const float4*)(red + base + cB);
                    yv[r][0] += v0.x; yv[r][1] += v0.y; yv[r][2] += v0.z; yv[r][3] += v0.w;
                    yv[r][4] += v1.x; yv[r][5] += v1.y; yv[r][6] += v1.z; yv[r][7] += v1.w;
                }
                const int nn = n0 + row;
                if (nn < N) {
                    *(float4*)(mypart + (long)nn * 64 + cA) =
                        make_float4(yv[r][0], yv[r][1], yv[r][2], yv[r][3]);
                    *(float4*)(mypart + (long)nn * 64 + cB) =
                        make_float4(yv[r][4], yv[r][5], yv[r][6], yv[r][7]);
                }
            }
        }
        __syncthreads();
        if (tid == 0) {
            __threadfence();
            *sflag = atomicAdd(&g_ticket[tile], 1);
        }
        __syncthreads();
        const int am_second = (*sflag == 1);
        if (am_second) {
            __threadfence();
            if (iq == 0) {
#pragma unroll
                for (int r = 0; r < 4; ++r) {
                    const int row = rg + 8 * r;
                    const int nn = n0 + row;
                    if (nn < N) {
                        float4 pA = *(const float4*)(otherpart + (long)nn * 64 + cA);
                        float4 pB = *(const float4*)(otherpart + (long)nn * 64 + cB);
                        float o[8];
                        o[0] = yv[r][0] + pA.x + bsm[cA + 0];
                        o[1] = yv[r][1] + pA.y + bsm[cA + 1];
                        o[2] = yv[r][2] + pA.z + bsm[cA + 2];
                        o[3] = yv[r][3] + pA.w + bsm[cA + 3];
                        o[4] = yv[r][4] + pB.x + bsm[cB + 0];
                        o[5] = yv[r][5] + pB.y + bsm[cB + 1];
                        o[6] = yv[r][6] + pB.z + bsm[cB + 2];
                        o[7] = yv[r][7] + pB.w + bsm[cB + 3];
#pragma unroll
                        for (int j = 0; j < 8; ++j)
                            o[j] = (o[j] >= 0.f) ? o[j] : 0.01f * o[j];
                        *(float4*)(out + (long)nn * 64 + cA) = make_float4(o[0], o[1], o[2], o[3]);
                        *(float4*)(out + (long)nn * 64 + cB) = make_float4(o[4], o[5], o[6], o[7]);
                    }
                }
            }
            if (tid == 0) g_ticket[tile] = 0;
        }
        __syncthreads();
    }
}

// ============================================================================
// launch
// ============================================================================
extern "C" void kernel_launch(void* const* d_in, const int* in_sizes, int n_in,
                              void* d_out, int out_size)
{
    const float* msg = (const float*)d_in[0];
    const float* xj  = (const float*)d_in[2];
    const float* eij = (const float*)d_in[3];
    const int*   idx = (const int*)d_in[4];
    const float* kc  = (const float*)d_in[6];
    const float* W   = (const float*)d_in[7];
    const float* b   = (const float*)d_in[8];
    float* out = (float*)d_out;

    const int E = in_sizes[0] / 64;
    const int N = out_size / 64;

    void* degp = nullptr;
    cudaGetSymbolAddress(&degp, g_deg);
    cudaMemsetAsync(degp, 0, (size_t)N * sizeof(int), 0);

    cudaFuncSetAttribute(k_weights, cudaFuncAttributeMaxDynamicSharedMemorySize, K1_SMEM);
    cudaFuncSetAttribute(k_agg_gemm, cudaFuncAttributeMaxDynamicSharedMemorySize, K4_SMEM);

    int eb = (E + 255) / 256;
    k_weights<<<eb, 256, K1_SMEM>>>(xj, eij, idx, kc, E);

    int sms = 148;
    cudaDeviceGetAttribute(&sms, cudaDevAttrMultiProcessorCount, 0);
    int nTiles = (N + 31) / 32;
    int nPairs = sms < nTiles ? sms : nTiles;
    k_agg_gemm<<<2 * nPairs, 256, K4_SMEM>>>(msg, W, b, out, N, nTiles);
}